// round 10
// baseline (speedup 1.0000x reference)
#include <cuda_runtime.h>
#include <cuda_fp16.h>
#include <cstdint>
#include <math.h>

// Problem constants
#define Bsz 4
#define Sq  2048
#define Dm  1024
#define Hh  16
#define HD  64
#define MTOT (Bsz * Sq)   // 8192
#define NEL ((size_t)MTOT * Dm)   // 8M
#define WEL ((size_t)Dm * Dm)     // 1M

// Scratch (device globals — no allocation allowed). All fp16.
__device__ __half g_qc[NEL];        // fp16(0.125 * q)
__device__ __half g_kc[NEL];
__device__ __half g_vc[NEL];
__device__ __half g_wc[4 * WEL];
__device__ __half g_xq[NEL];
__device__ __half g_xk[NEL];
__device__ __half g_xv[NEL];
__device__ __half g_ao[NEL];

// ===========================================================================
// Helpers
// ===========================================================================
__device__ __forceinline__ uint32_t smem_u32(const void* p) {
    uint32_t a;
    asm("{ .reg .u64 t; cvta.to.shared.u64 t, %1; cvt.u32.u64 %0, t; }"
        : "=r"(a) : "l"(p));
    return a;
}
__device__ __forceinline__ void cp16(uint32_t dst, const void* src) {
    asm volatile("cp.async.cg.shared.global [%0], [%1], 16;"
                 :: "r"(dst), "l"(src));
}
__device__ __forceinline__ void cp_commit() {
    asm volatile("cp.async.commit_group;" ::: "memory");
}
template<int N> __device__ __forceinline__ void cp_wait() {
    asm volatile("cp.async.wait_group %0;" :: "n"(N) : "memory");
}
__device__ __forceinline__ uint32_t pack_h2(float a, float b) {
    __half2 h = __floats2half2_rn(a, b);
    return *reinterpret_cast<uint32_t*>(&h);
}
__device__ __forceinline__ void ldsm4(uint32_t* r, uint32_t a) {
    asm volatile("ldmatrix.sync.aligned.m8n8.x4.shared.b16 {%0,%1,%2,%3}, [%4];"
        : "=r"(r[0]), "=r"(r[1]), "=r"(r[2]), "=r"(r[3]) : "r"(a));
}
__device__ __forceinline__ void ldsm4t(uint32_t* r, uint32_t a) {
    asm volatile("ldmatrix.sync.aligned.m8n8.x4.trans.shared.b16 {%0,%1,%2,%3}, [%4];"
        : "=r"(r[0]), "=r"(r[1]), "=r"(r[2]), "=r"(r[3]) : "r"(a));
}
__device__ __forceinline__ void mma_f16(float* d, const uint32_t* a,
                                        uint32_t b0, uint32_t b1) {
    asm volatile(
        "mma.sync.aligned.m16n8k16.row.col.f32.f16.f16.f32 "
        "{%0,%1,%2,%3}, {%4,%5,%6,%7}, {%8,%9}, {%0,%1,%2,%3};"
        : "+f"(d[0]), "+f"(d[1]), "+f"(d[2]), "+f"(d[3])
        : "r"(a[0]), "r"(a[1]), "r"(a[2]), "r"(a[3]), "r"(b0), "r"(b1));
}

#define LDH 72

// ===========================================================================
// Fused pre-convert: fp32 -> fp16 for all 7 tensors.
// ===========================================================================
#define I4 (NEL / 4)
#define W4 (WEL / 4)

__global__ __launch_bounds__(256) void conv_all(
    const float* __restrict__ q, const float* __restrict__ k,
    const float* __restrict__ v, const float* __restrict__ wq,
    const float* __restrict__ wk, const float* __restrict__ wv,
    const float* __restrict__ wo)
{
    size_t i = (size_t)blockIdx.x * 256 + threadIdx.x;
    const float* src;
    __half* dst;
    size_t off;
    float sc = 1.f;
    if (i < I4)            { src = q; dst = g_qc; off = i; sc = 0.125f; }
    else if (i < 2 * I4)   { src = k; dst = g_kc; off = i - I4; }
    else if (i < 3 * I4)   { src = v; dst = g_vc; off = i - 2 * I4; }
    else {
        size_t j = i - 3 * I4;
        int w = (int)(j / W4);
        off = j % W4;
        src = (w == 0) ? wq : (w == 1) ? wk : (w == 2) ? wv : wo;
        dst = g_wc + (size_t)w * WEL;
    }
    float4 x = reinterpret_cast<const float4*>(src)[off];
    uint2 u = make_uint2(pack_h2(x.x * sc, x.y * sc),
                         pack_h2(x.z * sc, x.w * sc));
    reinterpret_cast<uint2*>(dst)[off] = u;
}
#define CONV_BLOCKS ((int)((3 * I4 + 4 * W4 + 255) / 256))

// ===========================================================================
// fp16 tensor-core GEMM, 128x128 tile, BK=64, 3-stage ring, 1 barrier/chunk.
// ===========================================================================
#define BK 64
#define NC (Dm / BK)                   // 16
#define OP_BYTES (128 * LDH * 2)       // 18432
#define STAGE_BYTES (2 * OP_BYTES)     // 36864
#define GSTAGES 3
#define GSMEM (GSTAGES * STAGE_BYTES)  // 110592

__device__ __forceinline__ void load_chunk(uint32_t sbase, int stage,
                                           const __half* A, const __half* W,
                                           int row0, int col0, int kb, int tid) {
    uint32_t a_st = sbase + stage * STAGE_BYTES;
    uint32_t w_st = a_st + OP_BYTES;
    #pragma unroll
    for (int p = 0; p < 4; p++) {
        int idx = tid + p * 256;
        int r  = idx >> 3;
        int cq = idx & 7;
        uint32_t d = (uint32_t)(r * (LDH * 2) + cq * 16);
        cp16(a_st + d, A + (size_t)(row0 + r) * Dm + kb + cq * 8);
        cp16(w_st + d, W + (size_t)(col0 + r) * Dm + kb + cq * 8);
    }
    cp_commit();
}

__global__ __launch_bounds__(256, 2) void gemm_tc(float* __restrict__ Cp,
                                                  int asel, int wsel, int csel)
{
    extern __shared__ char smem[];
    uint32_t sbase = smem_u32(smem);
    const int az = (asel < 0) ? (int)blockIdx.z : asel;
    const int wz = (asel < 0) ? (int)blockIdx.z : wsel;
    const int cz = (asel < 0) ? (int)blockIdx.z + 1 : csel;

    const __half* A = (az == 0) ? g_qc : (az == 1) ? g_kc
                     : (az == 2) ? g_vc : g_ao;
    const __half* W = g_wc + (size_t)wz * WEL;
    __half* Cu = (cz == 1) ? g_xq : (cz == 2) ? g_xk : g_xv;

    const int tid = threadIdx.x;
    const int wid = tid >> 5;
    const int lid = tid & 31;
    const int g   = lid >> 2;
    const int tg  = lid & 3;
    const int wr  = wid >> 2;
    const int wc  = wid & 3;
    const int row0 = blockIdx.y * 128;
    const int col0 = blockIdx.x * 128;

    const int sub = lid >> 3, lr = lid & 7;
    const uint32_t lane_off = (uint32_t)(((sub & 1) * 8 + lr) * LDH + (sub >> 1) * 8) * 2;

    float acc[4][4][4];
    #pragma unroll
    for (int mt = 0; mt < 4; mt++)
        #pragma unroll
        for (int nt = 0; nt < 4; nt++)
            #pragma unroll
            for (int q = 0; q < 4; q++) acc[mt][nt][q] = 0.f;

    load_chunk(sbase, 0, A, W, row0, col0, 0, tid);
    load_chunk(sbase, 1, A, W, row0, col0, BK, tid);

    for (int c = 0; c < NC; c++) {
        if (c < NC - 1) cp_wait<1>(); else cp_wait<0>();
        __syncthreads();                    // chunk c visible; stage (c+2)%3 free
        if (c + 2 < NC)
            load_chunk(sbase, (c + 2) % 3, A, W, row0, col0, (c + 2) * BK, tid);

        uint32_t a_base = sbase + (c % 3) * STAGE_BYTES + lane_off;
        uint32_t w_base = a_base + OP_BYTES;

        #pragma unroll
        for (int ks = 0; ks < 4; ks++) {
            const uint32_t k0b = (uint32_t)(ks * 16) * 2;
            uint32_t af[4][4];
            #pragma unroll
            for (int mt = 0; mt < 4; mt++)
                ldsm4(af[mt], a_base + (uint32_t)((wr * 64 + mt * 16) * LDH) * 2 + k0b);
            #pragma unroll
            for (int ntp = 0; ntp < 2; ntp++) {
                uint32_t bq[4];
                ldsm4(bq, w_base + (uint32_t)((wc * 32 + ntp * 16) * LDH) * 2 + k0b);
                #pragma unroll
                for (int mt = 0; mt < 4; mt++) {
                    mma_f16(acc[mt][2 * ntp],     af[mt], bq[0], bq[2]);
                    mma_f16(acc[mt][2 * ntp + 1], af[mt], bq[1], bq[3]);
                }
            }
        }
    }

    #pragma unroll
    for (int mt = 0; mt < 4; mt++) {
        int row = row0 + wr * 64 + mt * 16 + g;
        #pragma unroll
        for (int nt = 0; nt < 4; nt++) {
            int col = col0 + wc * 32 + nt * 8 + 2 * tg;
            if (cz == 0) {
                *reinterpret_cast<float2*>(&Cp[(size_t)row * Dm + col]) =
                    make_float2(acc[mt][nt][0], acc[mt][nt][1]);
                *reinterpret_cast<float2*>(&Cp[(size_t)(row + 8) * Dm + col]) =
                    make_float2(acc[mt][nt][2], acc[mt][nt][3]);
            } else {
                *reinterpret_cast<uint32_t*>(&Cu[(size_t)row * Dm + col]) =
                    pack_h2(acc[mt][nt][0], acc[mt][nt][1]);
                *reinterpret_cast<uint32_t*>(&Cu[(size_t)(row + 8) * Dm + col]) =
                    pack_h2(acc[mt][nt][2], acc[mt][nt][3]);
            }
        }
    }
}

// ===========================================================================
// Flash attention (causal), fp16 mma, register-resident P, 3-stage KV ring.
// BQ=128 (8 warps x 16 rows), BKV=64, HD=64, 256 threads, 2 CTAs/SM.
// ===========================================================================
#define QS_OFF 0                               // [128][LDH] 18432 B
#define KS_OFF (128 * LDH * 2)                 // 3 x [64][LDH]
#define KV_STAGE (64 * LDH * 2)                // 9216
#define VS_OFF (KS_OFF + 3 * KV_STAGE)
#define AT_SMEM (VS_OFF + 3 * KV_STAGE)        // 73728 B

__device__ __forceinline__ void load_kv(uint32_t sbase, int stage,
                                        const __half* Kp, const __half* Vp,
                                        int jt, int tid) {
    uint32_t k_st = sbase + KS_OFF + stage * KV_STAGE;
    uint32_t v_st = sbase + VS_OFF + stage * KV_STAGE;
    #pragma unroll
    for (int p = 0; p < 2; p++) {
        int idx = tid + p * 256;
        int r   = idx >> 3;
        int cq  = idx & 7;
        size_t goff = (size_t)(jt * 64 + r) * Dm + cq * 8;
        uint32_t d = (uint32_t)(r * (LDH * 2) + cq * 16);
        cp16(k_st + d, Kp + goff);
        cp16(v_st + d, Vp + goff);
    }
    cp_commit();
}

__global__ __launch_bounds__(256, 2) void flash_attn_tc()
{
    extern __shared__ char smem[];
    uint32_t sbase = smem_u32(smem);

    const int qt = (gridDim.x - 1) - blockIdx.x;   // heavy tiles first
    const int bh = blockIdx.y;
    const int b  = bh >> 4;
    const int h  = bh & 15;
    const int q0 = qt * 128;

    const size_t base = (size_t)b * Sq * Dm + (size_t)h * HD;
    const __half* Qp = g_xq + base;
    const __half* Kp = g_xk + base;
    const __half* Vp = g_xv + base;
    __half*       Op = g_ao + base;

    const int tid = threadIdx.x;
    const int wid = tid >> 5;
    const int lid = tid & 31;
    const int g   = lid >> 2;
    const int tg  = lid & 3;
    const int wrow = wid * 16;
    const int ntl = 2 * qt + 2;                    // >= 2 always

    const int sub = lid >> 3, lr = lid & 7;
    const uint32_t lane_off = (uint32_t)(((sub & 1) * 8 + lr) * LDH + (sub >> 1) * 8) * 2;

    // ---- Prologue: Q (group 0), kv0 (group 1), kv1 (group 2) --------------
    {
        uint32_t q_st = sbase + QS_OFF;
        #pragma unroll
        for (int p = 0; p < 4; p++) {
            int idx = tid + p * 256;
            int r   = idx >> 3;
            int cq  = idx & 7;
            cp16(q_st + (uint32_t)(r * (LDH * 2) + cq * 16),
                 Qp + (size_t)(q0 + r) * Dm + cq * 8);
        }
        cp_commit();
    }
    load_kv(sbase, 0, Kp, Vp, 0, tid);
    load_kv(sbase, 1, Kp, Vp, 1, tid);
    cp_wait<2>();                 // Q resident
    __syncthreads();

    uint32_t qf[4][4];
    {
        uint32_t qb = sbase + QS_OFF + (uint32_t)(wrow * LDH) * 2 + lane_off;
        #pragma unroll
        for (int kt = 0; kt < 4; kt++)
            ldsm4(qf[kt], qb + (uint32_t)(kt * 16) * 2);
    }

    float m0 = -1e30f, m1 = -1e30f, l0 = 0.f, l1 = 0.f;
    float o[8][4];
    #pragma unroll
    for (int nt = 0; nt < 8; nt++)
        #pragma unroll
        for (int q = 0; q < 4; q++) o[nt][q] = 0.f;

    const int row_g  = q0 + wrow + g;
    const int row_g8 = row_g + 8;

    for (int jt = 0; jt < ntl; jt++) {
        if (jt < ntl - 1) cp_wait<1>(); else cp_wait<0>();
        __syncthreads();                      // kv(jt) visible; stage (jt+2)%3 free
        if (jt + 2 < ntl)
            load_kv(sbase, (jt + 2) % 3, Kp, Vp, jt + 2, tid);

        if (jt * 64 <= q0 + wrow + 15) {
            const int s = jt % 3;
            uint32_t k_base = sbase + KS_OFF + s * KV_STAGE + lane_off;
            uint32_t v_base = sbase + VS_OFF + s * KV_STAGE + lane_off;

            // ---- S = Q K^T ----
            float sacc[8][4];
            #pragma unroll
            for (int nt = 0; nt < 8; nt++)
                #pragma unroll
                for (int q = 0; q < 4; q++) sacc[nt][q] = 0.f;

            #pragma unroll
            for (int kt = 0; kt < 4; kt++) {
                const uint32_t k0b = (uint32_t)(kt * 16) * 2;
                #pragma unroll
                for (int ntp = 0; ntp < 4; ntp++) {
                    uint32_t bq[4];
                    ldsm4(bq, k_base + (uint32_t)((ntp * 16) * LDH) * 2 + k0b);
                    mma_f16(sacc[2 * ntp],     qf[kt], bq[0], bq[2]);
                    mma_f16(sacc[2 * ntp + 1], qf[kt], bq[1], bq[3]);
                }
            }

            // ---- Causal mask (diagonal tiles only) ----
            if (jt >= 2 * qt) {
                #pragma unroll
                for (int nt = 0; nt < 8; nt++) {
                    int cb = jt * 64 + nt * 8 + 2 * tg;
                    if (cb     > row_g ) sacc[nt][0] = -1e30f;
                    if (cb + 1 > row_g ) sacc[nt][1] = -1e30f;
                    if (cb     > row_g8) sacc[nt][2] = -1e30f;
                    if (cb + 1 > row_g8) sacc[nt][3] = -1e30f;
                }
            }

            // ---- Online softmax (register-resident P) ----
            float mn0 = m0, mn1 = m1;
            #pragma unroll
            for (int nt = 0; nt < 8; nt++) {
                mn0 = fmaxf(mn0, fmaxf(sacc[nt][0], sacc[nt][1]));
                mn1 = fmaxf(mn1, fmaxf(sacc[nt][2], sacc[nt][3]));
            }
            mn0 = fmaxf(mn0, __shfl_xor_sync(0xffffffffu, mn0, 1));
            mn0 = fmaxf(mn0, __shfl_xor_sync(0xffffffffu, mn0, 2));
            mn1 = fmaxf(mn1, __shfl_xor_sync(0xffffffffu, mn1, 1));
            mn1 = fmaxf(mn1, __shfl_xor_sync(0xffffffffu, mn1, 2));

            float sc0 = __expf(m0 - mn0);
            float sc1 = __expf(m1 - mn1);
            m0 = mn0; m1 = mn1;

            uint32_t ph[8][2];
            float ls0 = 0.f, ls1 = 0.f;
            #pragma unroll
            for (int nt = 0; nt < 8; nt++) {
                float p0 = __expf(sacc[nt][0] - mn0);
                float p1 = __expf(sacc[nt][1] - mn0);
                float p2 = __expf(sacc[nt][2] - mn1);
                float p3 = __expf(sacc[nt][3] - mn1);
                ls0 += p0 + p1;
                ls1 += p2 + p3;
                ph[nt][0] = pack_h2(p0, p1);   // A-frag rows g,   k=2tg..
                ph[nt][1] = pack_h2(p2, p3);   // A-frag rows g+8
            }
            ls0 += __shfl_xor_sync(0xffffffffu, ls0, 1);
            ls0 += __shfl_xor_sync(0xffffffffu, ls0, 2);
            ls1 += __shfl_xor_sync(0xffffffffu, ls1, 1);
            ls1 += __shfl_xor_sync(0xffffffffu, ls1, 2);
            l0 = l0 * sc0 + ls0;
            l1 = l1 * sc1 + ls1;

            #pragma unroll
            for (int nt = 0; nt < 8; nt++) {
                o[nt][0] *= sc0; o[nt][1] *= sc0;
                o[nt][2] *= sc1; o[nt][3] *= sc1;
            }

            // ---- O += P V (P from registers, V via ldmatrix.trans) ----
            #pragma unroll
            for (int kt = 0; kt < 4; kt++) {
                uint32_t ap[4];
                ap[0] = ph[2 * kt][0];
                ap[1] = ph[2 * kt][1];
                ap[2] = ph[2 * kt + 1][0];
                ap[3] = ph[2 * kt + 1][1];
                #pragma unroll
                for (int ntp = 0; ntp < 4; ntp++) {
                    uint32_t bq[4];
                    ldsm4t(bq, v_base + (uint32_t)(kt * 16 * LDH + ntp * 16) * 2);
                    mma_f16(o[2 * ntp],     ap, bq[0], bq[1]);
                    mma_f16(o[2 * ntp + 1], ap, bq[2], bq[3]);
                }
            }
        }
    }

    // ---- Epilogue: normalize, write fp16 O ----
    float il0 = 1.f / l0, il1 = 1.f / l1;
    #pragma unroll
    for (int nt = 0; nt < 8; nt++) {
        int col = nt * 8 + 2 * tg;
        *reinterpret_cast<uint32_t*>(&Op[(size_t)(row_g) * Dm + col]) =
            pack_h2(o[nt][0] * il0, o[nt][1] * il0);
        *reinterpret_cast<uint32_t*>(&Op[(size_t)(row_g8) * Dm + col]) =
            pack_h2(o[nt][2] * il1, o[nt][3] * il1);
    }
}

// ---------------------------------------------------------------------------
// Launch
// ---------------------------------------------------------------------------
extern "C" void kernel_launch(void* const* d_in, const int* in_sizes, int n_in,
                              void* d_out, int out_size)
{
    const float* q  = (const float*)d_in[0];
    const float* k  = (const float*)d_in[1];
    const float* v  = (const float*)d_in[2];
    const float* wq = (const float*)d_in[3];
    const float* wk = (const float*)d_in[4];
    const float* wv = (const float*)d_in[5];
    const float* wo = (const float*)d_in[6];
    float* out = (float*)d_out;

    cudaFuncSetAttribute(gemm_tc, cudaFuncAttributeMaxDynamicSharedMemorySize,
                         GSMEM);
    cudaFuncSetAttribute(flash_attn_tc,
                         cudaFuncAttributeMaxDynamicSharedMemorySize, AT_SMEM);

    conv_all<<<CONV_BLOCKS, 256>>>(q, k, v, wq, wk, wv, wo);

    dim3 gqkv(Dm / 128, MTOT / 128, 3);    // fused Q/K/V projections
    gemm_tc<<<gqkv, 256, GSMEM>>>(nullptr, -1, 0, 0);

    dim3 agrid(Sq / 128, Bsz * Hh, 1);     // (16, 64)
    flash_attn_tc<<<agrid, 256, AT_SMEM>>>();

    dim3 ggrid(Dm / 128, MTOT / 128, 1);   // O projection
    gemm_tc<<<ggrid, 256, GSMEM>>>(out, 3, 3, 0);
}

// round 11
// speedup vs baseline: 1.5211x; 1.5211x over previous
#include <cuda_runtime.h>
#include <cuda_fp16.h>
#include <cstdint>
#include <math.h>

// Problem constants
#define Bsz 4
#define Sq  2048
#define Dm  1024
#define Hh  16
#define HD  64
#define MTOT (Bsz * Sq)   // 8192
#define NEL ((size_t)MTOT * Dm)   // 8M
#define WEL ((size_t)Dm * Dm)     // 1M

// Scratch (device globals — no allocation allowed). All fp16.
__device__ __half g_qc[NEL];        // fp16(0.125 * q)
__device__ __half g_kc[NEL];
__device__ __half g_vc[NEL];
__device__ __half g_wc[4 * WEL];
__device__ __half g_xq[NEL];
__device__ __half g_xk[NEL];
__device__ __half g_xv[NEL];
__device__ __half g_ao[NEL];

// ===========================================================================
// Helpers
// ===========================================================================
__device__ __forceinline__ uint32_t smem_u32(const void* p) {
    uint32_t a;
    asm("{ .reg .u64 t; cvta.to.shared.u64 t, %1; cvt.u32.u64 %0, t; }"
        : "=r"(a) : "l"(p));
    return a;
}
__device__ __forceinline__ void cp16(uint32_t dst, const void* src) {
    asm volatile("cp.async.cg.shared.global [%0], [%1], 16;"
                 :: "r"(dst), "l"(src));
}
__device__ __forceinline__ void cp_commit() {
    asm volatile("cp.async.commit_group;" ::: "memory");
}
template<int N> __device__ __forceinline__ void cp_wait() {
    asm volatile("cp.async.wait_group %0;" :: "n"(N) : "memory");
}
__device__ __forceinline__ uint32_t pack_h2(float a, float b) {
    __half2 h = __floats2half2_rn(a, b);
    return *reinterpret_cast<uint32_t*>(&h);
}
__device__ __forceinline__ void ldsm4(uint32_t* r, uint32_t a) {
    asm volatile("ldmatrix.sync.aligned.m8n8.x4.shared.b16 {%0,%1,%2,%3}, [%4];"
        : "=r"(r[0]), "=r"(r[1]), "=r"(r[2]), "=r"(r[3]) : "r"(a));
}
__device__ __forceinline__ void ldsm4t(uint32_t* r, uint32_t a) {
    asm volatile("ldmatrix.sync.aligned.m8n8.x4.trans.shared.b16 {%0,%1,%2,%3}, [%4];"
        : "=r"(r[0]), "=r"(r[1]), "=r"(r[2]), "=r"(r[3]) : "r"(a));
}
// D(16x8) += A(16x16) * B(16x8), fp16 in, fp32 accumulate
__device__ __forceinline__ void mma_f16(float* d, const uint32_t* a,
                                        uint32_t b0, uint32_t b1) {
    asm volatile(
        "mma.sync.aligned.m16n8k16.row.col.f32.f16.f16.f32 "
        "{%0,%1,%2,%3}, {%4,%5,%6,%7}, {%8,%9}, {%0,%1,%2,%3};"
        : "+f"(d[0]), "+f"(d[1]), "+f"(d[2]), "+f"(d[3])
        : "r"(a[0]), "r"(a[1]), "r"(a[2]), "r"(a[3]), "r"(b0), "r"(b1));
}

#define LDH 72

// ===========================================================================
// Fused pre-convert: fp32 -> fp16 for all 7 tensors (float4 granularity).
// ===========================================================================
#define I4 (NEL / 4)
#define W4 (WEL / 4)

__global__ __launch_bounds__(256) void conv_all(
    const float* __restrict__ q, const float* __restrict__ k,
    const float* __restrict__ v, const float* __restrict__ wq,
    const float* __restrict__ wk, const float* __restrict__ wv,
    const float* __restrict__ wo)
{
    size_t i = (size_t)blockIdx.x * 256 + threadIdx.x;
    const float* src;
    __half* dst;
    size_t off;
    float sc = 1.f;
    if (i < I4)            { src = q; dst = g_qc; off = i; sc = 0.125f; }
    else if (i < 2 * I4)   { src = k; dst = g_kc; off = i - I4; }
    else if (i < 3 * I4)   { src = v; dst = g_vc; off = i - 2 * I4; }
    else {
        size_t j = i - 3 * I4;
        int w = (int)(j / W4);
        off = j % W4;
        src = (w == 0) ? wq : (w == 1) ? wk : (w == 2) ? wv : wo;
        dst = g_wc + (size_t)w * WEL;
    }
    float4 x = reinterpret_cast<const float4*>(src)[off];
    uint2 u = make_uint2(pack_h2(x.x * sc, x.y * sc),
                         pack_h2(x.z * sc, x.w * sc));
    reinterpret_cast<uint2*>(dst)[off] = u;
}
#define CONV_BLOCKS ((int)((3 * I4 + 4 * W4 + 255) / 256))

// ===========================================================================
// fp16 tensor-core GEMM (R9 proven version): 128x128 tile, BK=64 halves,
// 2-stage double buffer, 2 CTAs/SM, ldmatrix fragments.
// ===========================================================================
#define BK 64
#define NC (Dm / BK)                   // 16
#define OP_BYTES (128 * LDH * 2)       // 18432 per operand per stage
#define STAGE_BYTES (2 * OP_BYTES)     // 36864 (A then W)
#define GSMEM (2 * STAGE_BYTES)        // 73728

__device__ __forceinline__ void load_chunk(uint32_t sbase, int stage,
                                           const __half* A, const __half* W,
                                           int row0, int col0, int kb, int tid) {
    uint32_t a_st = sbase + stage * STAGE_BYTES;
    uint32_t w_st = a_st + OP_BYTES;
    #pragma unroll
    for (int p = 0; p < 4; p++) {
        int idx = tid + p * 256;          // 0..1023
        int r  = idx >> 3;                // 0..127
        int cq = idx & 7;                 // 16B unit within 128B row
        uint32_t d = (uint32_t)(r * (LDH * 2) + cq * 16);
        cp16(a_st + d, A + (size_t)(row0 + r) * Dm + kb + cq * 8);
        cp16(w_st + d, W + (size_t)(col0 + r) * Dm + kb + cq * 8);
    }
    cp_commit();
}

__global__ __launch_bounds__(256, 2) void gemm_tc(float* __restrict__ Cp,
                                                  int asel, int wsel, int csel)
{
    extern __shared__ char smem[];
    uint32_t sbase = smem_u32(smem);
    const int az = (asel < 0) ? (int)blockIdx.z : asel;
    const int wz = (asel < 0) ? (int)blockIdx.z : wsel;
    const int cz = (asel < 0) ? (int)blockIdx.z + 1 : csel;

    const __half* A = (az == 0) ? g_qc : (az == 1) ? g_kc
                     : (az == 2) ? g_vc : g_ao;
    const __half* W = g_wc + (size_t)wz * WEL;
    __half* Cu = (cz == 1) ? g_xq : (cz == 2) ? g_xk : g_xv;

    const int tid = threadIdx.x;
    const int wid = tid >> 5;
    const int lid = tid & 31;
    const int g   = lid >> 2;
    const int tg  = lid & 3;
    const int wr  = wid >> 2;              // warp row 0..1 (64 rows)
    const int wc  = wid & 3;               // warp col 0..3 (32 cols)
    const int row0 = blockIdx.y * 128;
    const int col0 = blockIdx.x * 128;

    // ldmatrix lane offset (halves)
    const int sub = lid >> 3, lr = lid & 7;
    const uint32_t lane_off = (uint32_t)(((sub & 1) * 8 + lr) * LDH + (sub >> 1) * 8) * 2;

    float acc[4][4][4];
    #pragma unroll
    for (int mt = 0; mt < 4; mt++)
        #pragma unroll
        for (int nt = 0; nt < 4; nt++)
            #pragma unroll
            for (int q = 0; q < 4; q++) acc[mt][nt][q] = 0.f;

    load_chunk(sbase, 0, A, W, row0, col0, 0, tid);

    for (int c = 0; c < NC; c++) {
        if (c + 1 < NC) {
            load_chunk(sbase, (c + 1) & 1, A, W, row0, col0, (c + 1) * BK, tid);
            cp_wait<1>();
        } else {
            cp_wait<0>();
        }
        __syncthreads();

        uint32_t a_base = sbase + (c & 1) * STAGE_BYTES + lane_off;
        uint32_t w_base = a_base + OP_BYTES;

        #pragma unroll
        for (int ks = 0; ks < 4; ks++) {
            const uint32_t k0b = (uint32_t)(ks * 16) * 2;
            uint32_t af[4][4];
            #pragma unroll
            for (int mt = 0; mt < 4; mt++)
                ldsm4(af[mt], a_base + (uint32_t)((wr * 64 + mt * 16) * LDH) * 2 + k0b);
            #pragma unroll
            for (int ntp = 0; ntp < 2; ntp++) {
                uint32_t bq[4];
                ldsm4(bq, w_base + (uint32_t)((wc * 32 + ntp * 16) * LDH) * 2 + k0b);
                #pragma unroll
                for (int mt = 0; mt < 4; mt++) {
                    mma_f16(acc[mt][2 * ntp],     af[mt], bq[0], bq[2]);
                    mma_f16(acc[mt][2 * ntp + 1], af[mt], bq[1], bq[3]);
                }
            }
        }
        __syncthreads();
    }

    #pragma unroll
    for (int mt = 0; mt < 4; mt++) {
        int row = row0 + wr * 64 + mt * 16 + g;
        #pragma unroll
        for (int nt = 0; nt < 4; nt++) {
            int col = col0 + wc * 32 + nt * 8 + 2 * tg;
            if (cz == 0) {
                *reinterpret_cast<float2*>(&Cp[(size_t)row * Dm + col]) =
                    make_float2(acc[mt][nt][0], acc[mt][nt][1]);
                *reinterpret_cast<float2*>(&Cp[(size_t)(row + 8) * Dm + col]) =
                    make_float2(acc[mt][nt][2], acc[mt][nt][3]);
            } else {
                *reinterpret_cast<uint32_t*>(&Cu[(size_t)row * Dm + col]) =
                    pack_h2(acc[mt][nt][0], acc[mt][nt][1]);
                *reinterpret_cast<uint32_t*>(&Cu[(size_t)(row + 8) * Dm + col]) =
                    pack_h2(acc[mt][nt][2], acc[mt][nt][3]);
            }
        }
    }
}

// ===========================================================================
// Flash attention (causal), fp16 mma, register-resident P,
// 2-stage double-buffered KV (R9 structure), 2 CTAs/SM.
// BQ=128 (8 warps x 16 rows), BKV=64, HD=64, 256 threads.
// ===========================================================================
#define QS_OFF 0                               // [128][LDH] 18432 B
#define KS_OFF (128 * LDH * 2)                 // 2 x [64][LDH] 9216 B each
#define KV_STAGE (64 * LDH * 2)                // 9216
#define VS_OFF (KS_OFF + 2 * KV_STAGE)
#define AT_SMEM (VS_OFF + 2 * KV_STAGE)        // 55296 B

__device__ __forceinline__ void load_kv(uint32_t sbase, int stage,
                                        const __half* Kp, const __half* Vp,
                                        int jt, int tid) {
    uint32_t k_st = sbase + KS_OFF + stage * KV_STAGE;
    uint32_t v_st = sbase + VS_OFF + stage * KV_STAGE;
    #pragma unroll
    for (int p = 0; p < 2; p++) {
        int idx = tid + p * 256;       // 0..511
        int r   = idx >> 3;            // 0..63
        int cq  = idx & 7;
        size_t goff = (size_t)(jt * 64 + r) * Dm + cq * 8;
        uint32_t d = (uint32_t)(r * (LDH * 2) + cq * 16);
        cp16(k_st + d, Kp + goff);
        cp16(v_st + d, Vp + goff);
    }
    cp_commit();
}

__global__ __launch_bounds__(256, 2) void flash_attn_tc()
{
    extern __shared__ char smem[];
    uint32_t sbase = smem_u32(smem);

    const int qt = (gridDim.x - 1) - blockIdx.x;   // heavy tiles first
    const int bh = blockIdx.y;
    const int b  = bh >> 4;
    const int h  = bh & 15;
    const int q0 = qt * 128;

    const size_t base = (size_t)b * Sq * Dm + (size_t)h * HD;
    const __half* Qp = g_xq + base;
    const __half* Kp = g_xk + base;
    const __half* Vp = g_xv + base;
    __half*       Op = g_ao + base;

    const int tid = threadIdx.x;
    const int wid = tid >> 5;
    const int lid = tid & 31;
    const int g   = lid >> 2;
    const int tg  = lid & 3;
    const int wrow = wid * 16;
    const int ntl = 2 * qt + 2;

    const int sub = lid >> 3, lr = lid & 7;
    const uint32_t lane_off = (uint32_t)(((sub & 1) * 8 + lr) * LDH + (sub >> 1) * 8) * 2;

    // ---- Prologue: stage Q (group 0), KV tile 0 (group 1) -----------------
    {
        uint32_t q_st = sbase + QS_OFF;
        #pragma unroll
        for (int p = 0; p < 4; p++) {
            int idx = tid + p * 256;       // 0..1023
            int r   = idx >> 3;            // 0..127
            int cq  = idx & 7;
            cp16(q_st + (uint32_t)(r * (LDH * 2) + cq * 16),
                 Qp + (size_t)(q0 + r) * Dm + cq * 8);
        }
        cp_commit();
    }
    load_kv(sbase, 0, Kp, Vp, 0, tid);
    cp_wait<1>();                // Q resident (groups complete in order)
    __syncthreads();

    // Cache Q fragments (16 regs)
    uint32_t qf[4][4];
    {
        uint32_t qb = sbase + QS_OFF + (uint32_t)(wrow * LDH) * 2 + lane_off;
        #pragma unroll
        for (int kt = 0; kt < 4; kt++)
            ldsm4(qf[kt], qb + (uint32_t)(kt * 16) * 2);
    }

    float m0 = -1e30f, m1 = -1e30f, l0 = 0.f, l1 = 0.f;
    float o[8][4];
    #pragma unroll
    for (int nt = 0; nt < 8; nt++)
        #pragma unroll
        for (int q = 0; q < 4; q++) o[nt][q] = 0.f;

    const int row_g  = q0 + wrow + g;
    const int row_g8 = row_g + 8;

    for (int jt = 0; jt < ntl; jt++) {
        const int s = jt & 1;
        if (jt + 1 < ntl) {
            load_kv(sbase, s ^ 1, Kp, Vp, jt + 1, tid);
            cp_wait<1>();          // tile jt resident
        } else {
            cp_wait<0>();
        }
        __syncthreads();

        if (jt * 64 <= q0 + wrow + 15) {
            uint32_t k_base = sbase + KS_OFF + s * KV_STAGE + lane_off;
            uint32_t v_base = sbase + VS_OFF + s * KV_STAGE + lane_off;

            // ---- S = Q K^T ----
            float sacc[8][4];
            #pragma unroll
            for (int nt = 0; nt < 8; nt++)
                #pragma unroll
                for (int q = 0; q < 4; q++) sacc[nt][q] = 0.f;

            #pragma unroll
            for (int kt = 0; kt < 4; kt++) {
                const uint32_t k0b = (uint32_t)(kt * 16) * 2;
                #pragma unroll
                for (int ntp = 0; ntp < 4; ntp++) {
                    uint32_t bq[4];
                    ldsm4(bq, k_base + (uint32_t)((ntp * 16) * LDH) * 2 + k0b);
                    mma_f16(sacc[2 * ntp],     qf[kt], bq[0], bq[2]);
                    mma_f16(sacc[2 * ntp + 1], qf[kt], bq[1], bq[3]);
                }
            }

            // ---- Causal mask (diagonal tiles only) ----
            if (jt >= 2 * qt) {
                #pragma unroll
                for (int nt = 0; nt < 8; nt++) {
                    int cb = jt * 64 + nt * 8 + 2 * tg;
                    if (cb     > row_g ) sacc[nt][0] = -1e30f;
                    if (cb + 1 > row_g ) sacc[nt][1] = -1e30f;
                    if (cb     > row_g8) sacc[nt][2] = -1e30f;
                    if (cb + 1 > row_g8) sacc[nt][3] = -1e30f;
                }
            }

            // ---- Online softmax (register-resident P) ----
            float mn0 = m0, mn1 = m1;
            #pragma unroll
            for (int nt = 0; nt < 8; nt++) {
                mn0 = fmaxf(mn0, fmaxf(sacc[nt][0], sacc[nt][1]));
                mn1 = fmaxf(mn1, fmaxf(sacc[nt][2], sacc[nt][3]));
            }
            mn0 = fmaxf(mn0, __shfl_xor_sync(0xffffffffu, mn0, 1));
            mn0 = fmaxf(mn0, __shfl_xor_sync(0xffffffffu, mn0, 2));
            mn1 = fmaxf(mn1, __shfl_xor_sync(0xffffffffu, mn1, 1));
            mn1 = fmaxf(mn1, __shfl_xor_sync(0xffffffffu, mn1, 2));

            float sc0 = __expf(m0 - mn0);
            float sc1 = __expf(m1 - mn1);
            m0 = mn0; m1 = mn1;

            uint32_t ph[8][2];
            float ls0 = 0.f, ls1 = 0.f;
            #pragma unroll
            for (int nt = 0; nt < 8; nt++) {
                float p0 = __expf(sacc[nt][0] - mn0);
                float p1 = __expf(sacc[nt][1] - mn0);
                float p2 = __expf(sacc[nt][2] - mn1);
                float p3 = __expf(sacc[nt][3] - mn1);
                ls0 += p0 + p1;
                ls1 += p2 + p3;
                ph[nt][0] = pack_h2(p0, p1);   // A-frag rows g
                ph[nt][1] = pack_h2(p2, p3);   // A-frag rows g+8
            }
            ls0 += __shfl_xor_sync(0xffffffffu, ls0, 1);
            ls0 += __shfl_xor_sync(0xffffffffu, ls0, 2);
            ls1 += __shfl_xor_sync(0xffffffffu, ls1, 1);
            ls1 += __shfl_xor_sync(0xffffffffu, ls1, 2);
            l0 = l0 * sc0 + ls0;
            l1 = l1 * sc1 + ls1;

            #pragma unroll
            for (int nt = 0; nt < 8; nt++) {
                o[nt][0] *= sc0; o[nt][1] *= sc0;
                o[nt][2] *= sc1; o[nt][3] *= sc1;
            }

            // ---- O += P V (P from registers, V via ldmatrix.trans) ----
            #pragma unroll
            for (int kt = 0; kt < 4; kt++) {
                uint32_t ap[4];
                ap[0] = ph[2 * kt][0];
                ap[1] = ph[2 * kt][1];
                ap[2] = ph[2 * kt + 1][0];
                ap[3] = ph[2 * kt + 1][1];
                #pragma unroll
                for (int ntp = 0; ntp < 4; ntp++) {
                    uint32_t bq[4];
                    ldsm4t(bq, v_base + (uint32_t)(kt * 16 * LDH + ntp * 16) * 2);
                    mma_f16(o[2 * ntp],     ap, bq[0], bq[1]);
                    mma_f16(o[2 * ntp + 1], ap, bq[2], bq[3]);
                }
            }
        }
        __syncthreads();   // stage s free for the prefetch issued next iter
    }

    // ---- Epilogue: normalize, write fp16 O ----
    float il0 = 1.f / l0, il1 = 1.f / l1;
    #pragma unroll
    for (int nt = 0; nt < 8; nt++) {
        int col = nt * 8 + 2 * tg;
        *reinterpret_cast<uint32_t*>(&Op[(size_t)(row_g) * Dm + col]) =
            pack_h2(o[nt][0] * il0, o[nt][1] * il0);
        *reinterpret_cast<uint32_t*>(&Op[(size_t)(row_g8) * Dm + col]) =
            pack_h2(o[nt][2] * il1, o[nt][3] * il1);
    }
}

// ---------------------------------------------------------------------------
// Launch
// ---------------------------------------------------------------------------
extern "C" void kernel_launch(void* const* d_in, const int* in_sizes, int n_in,
                              void* d_out, int out_size)
{
    const float* q  = (const float*)d_in[0];
    const float* k  = (const float*)d_in[1];
    const float* v  = (const float*)d_in[2];
    const float* wq = (const float*)d_in[3];
    const float* wk = (const float*)d_in[4];
    const float* wv = (const float*)d_in[5];
    const float* wo = (const float*)d_in[6];
    float* out = (float*)d_out;

    cudaFuncSetAttribute(gemm_tc, cudaFuncAttributeMaxDynamicSharedMemorySize,
                         GSMEM);
    cudaFuncSetAttribute(flash_attn_tc,
                         cudaFuncAttributeMaxDynamicSharedMemorySize, AT_SMEM);

    conv_all<<<CONV_BLOCKS, 256>>>(q, k, v, wq, wk, wv, wo);

    dim3 gqkv(Dm / 128, MTOT / 128, 3);    // fused Q/K/V projections
    gemm_tc<<<gqkv, 256, GSMEM>>>(nullptr, -1, 0, 0);

    dim3 agrid(Sq / 128, Bsz * Hh, 1);     // (16, 64)
    flash_attn_tc<<<agrid, 256, AT_SMEM>>>();

    dim3 ggrid(Dm / 128, MTOT / 128, 1);   // O projection
    gemm_tc<<<ggrid, 256, GSMEM>>>(out, 3, 3, 0);
}